// round 4
// baseline (speedup 1.0000x reference)
#include <cuda_runtime.h>
#include <cuda_fp16.h>
#include <math.h>
#include <stdint.h>

#define NB 4
#define CC 256
#define HWD 4096
#define NH 4
#define HD 64
#define NGRP 8
#define GC 32
#define EPSV 1e-5f
#define LOG2E 1.44269504088896340736f

// ---- scratch (allocation-free) ----
__device__ __half g_q16[NB * CC * HWD];
__device__ __half g_k16[NB * CC * HWD];
__device__ __half g_v16[NB * CC * HWD];
__device__ __half g_ao16[NB * CC * HWD];
__device__ __half g_xn16[NB * CC * HWD];
__device__ __half g_qw16[3 * CC * CC];
__device__ __half g_pw16[CC * CC];
__device__ float  g_part[256 * 2];

// ---------------- helpers ----------------
__device__ __forceinline__ float ex2(float x) {
    float y; asm("ex2.approx.ftz.f32 %0, %1;" : "=f"(y) : "f"(x)); return y;
}
__device__ __forceinline__ uint32_t h2ex2(uint32_t x) {
    uint32_t y; asm("ex2.approx.f16x2 %0, %1;" : "=r"(y) : "r"(x)); return y;
}
__device__ __forceinline__ uint32_t pack2(float a, float b) {
    __half2 h = __floats2half2_rn(a, b);
    return *reinterpret_cast<uint32_t*>(&h);
}
__device__ __forceinline__ uint32_t sptr(const void* p) {
    return (uint32_t)__cvta_generic_to_shared(p);
}
__device__ __forceinline__ void cp16(void* dst, const void* src) {
    asm volatile("cp.async.cg.shared.global [%0], [%1], 16;\n"
                 :: "r"(sptr(dst)), "l"(src));
}
__device__ __forceinline__ void ldsm4t(uint32_t* f, const void* p) {
    asm volatile("ldmatrix.sync.aligned.m8n8.x4.trans.shared.b16 {%0,%1,%2,%3}, [%4];\n"
                 : "=r"(f[0]), "=r"(f[1]), "=r"(f[2]), "=r"(f[3]) : "r"(sptr(p)));
}
__device__ __forceinline__ void ldsm4(uint32_t* f, const void* p) {
    asm volatile("ldmatrix.sync.aligned.m8n8.x4.shared.b16 {%0,%1,%2,%3}, [%4];\n"
                 : "=r"(f[0]), "=r"(f[1]), "=r"(f[2]), "=r"(f[3]) : "r"(sptr(p)));
}
__device__ __forceinline__ void mma16816(float* c, const uint32_t* a, uint32_t b0, uint32_t b1) {
    asm volatile(
        "mma.sync.aligned.m16n8k16.row.col.f32.f16.f16.f32 "
        "{%0,%1,%2,%3}, {%4,%5,%6,%7}, {%8,%9}, {%0,%1,%2,%3};\n"
        : "+f"(c[0]), "+f"(c[1]), "+f"(c[2]), "+f"(c[3])
        : "r"(a[0]), "r"(a[1]), "r"(a[2]), "r"(a[3]), "r"(b0), "r"(b1));
}

// ---------------- GroupNorm stats (partials) ----------------
__global__ void gn_part_kernel(const float* __restrict__ x) {
    int ng = blockIdx.x >> 3, part = blockIdx.x & 7;
    const float4* xp = (const float4*)(x + (size_t)ng * GC * HWD);
    float s = 0.f, ss = 0.f;
    int i0 = part * 4096;
    for (int i = i0 + threadIdx.x; i < i0 + 4096; i += 256) {
        float4 v = xp[i];
        s  += v.x + v.y + v.z + v.w;
        ss += v.x * v.x + v.y * v.y + v.z * v.z + v.w * v.w;
    }
    #pragma unroll
    for (int off = 16; off; off >>= 1) {
        s  += __shfl_down_sync(0xffffffffu, s, off);
        ss += __shfl_down_sync(0xffffffffu, ss, off);
    }
    __shared__ float sh[16];
    int w = threadIdx.x >> 5;
    if ((threadIdx.x & 31) == 0) { sh[w] = s; sh[8 + w] = ss; }
    __syncthreads();
    if (threadIdx.x == 0) {
        float S = 0.f, SS = 0.f;
        #pragma unroll
        for (int i = 0; i < 8; i++) { S += sh[i]; SS += sh[8 + i]; }
        g_part[blockIdx.x * 2] = S; g_part[blockIdx.x * 2 + 1] = SS;
    }
}

// ---------------- normalize x -> fp16 [c][hw] (inlines final GN reduce) ----------------
__global__ void prep_xn_kernel(const float* __restrict__ x,
                               const float* __restrict__ nw, const float* __restrict__ nb_) {
    int row = blockIdx.x;               // n*CC + c
    int n = row >> 8, c = row & 255;
    int grp = c / GC;
    int ng = n * NGRP + grp;
    float s = 0.f, ss = 0.f;
    #pragma unroll
    for (int p = 0; p < 8; p++) {
        s  += g_part[(ng * 8 + p) * 2];
        ss += g_part[(ng * 8 + p) * 2 + 1];
    }
    const float invn = 1.0f / (float)(GC * HWD);
    float m  = s * invn;
    float rs = rsqrtf(ss * invn - m * m + EPSV);
    float scv = rs * nw[c];
    float bcv = nb_[c] - m * scv;
    const float4* xp = (const float4*)(x + (size_t)row * HWD);
    __half* dst = g_xn16 + (size_t)row * HWD;
    #pragma unroll
    for (int i = 0; i < 4; i++) {
        int idx = threadIdx.x + 256 * i;
        float4 v = xp[idx];
        uint2 u;
        u.x = pack2(v.x * scv + bcv, v.y * scv + bcv);
        u.y = pack2(v.z * scv + bcv, v.w * scv + bcv);
        *(uint2*)&dst[idx * 4] = u;
    }
}

// ---------------- weights -> fp16 ----------------
__global__ void conv_w_kernel(const float* __restrict__ qw, const float* __restrict__ pw) {
    int i = blockIdx.x * 256 + threadIdx.x;
    if (i < 3 * CC * CC) g_qw16[i] = __float2half(qw[i]);
    if (i < CC * CC)     g_pw16[i] = __float2half(pw[i]);
}

// ---------------- fp16 tensor-core GEMM: QKV ----------------
__global__ __launch_bounds__(256, 2) void gemm_qkv16_kernel(const float* __restrict__ qkv_b) {
    const int n  = blockIdx.z;
    const int o0 = blockIdx.y * 128;
    const int j0 = blockIdx.x * 128;
    __shared__ __align__(16) __half As[2][128][40];
    __shared__ __align__(16) __half Bs[2][32][136];

    const int tid = threadIdx.x, w = tid >> 5, lane = tid & 31;
    const int wm = w >> 1, wn = w & 1;
    const int g = lane >> 2, t4 = lane & 3, mi = lane >> 3, r8 = lane & 7;
    const int la = lane & 15, ha = lane >> 4;
    const __half* xn = g_xn16 + (size_t)n * CC * HWD;

    auto prefetch = [&](int buf, int k0) {
        #pragma unroll
        for (int i = 0; i < 2; i++) {
            int s = tid + 256 * i;
            int row = s >> 2, c8 = (s & 3) * 8;
            cp16(&As[buf][row][c8], &g_qw16[(size_t)(o0 + row) * CC + k0 + c8]);
        }
        #pragma unroll
        for (int i = 0; i < 2; i++) {
            int s = tid + 256 * i;
            int row = s >> 4, c8 = (s & 15) * 8;
            cp16(&Bs[buf][row][c8], &xn[(size_t)(k0 + row) * HWD + j0 + c8]);
        }
        asm volatile("cp.async.commit_group;\n");
    };

    float acc[2][8][4] = {};
    prefetch(0, 0);
    for (int c = 0; c < 8; c++) {
        int buf = c & 1;
        if (c + 1 < 8) { prefetch(buf ^ 1, (c + 1) * 32); asm volatile("cp.async.wait_group 1;\n"); }
        else           { asm volatile("cp.async.wait_group 0;\n"); }
        __syncthreads();
        #pragma unroll
        for (int ks = 0; ks < 2; ks++) {
            uint32_t a[2][4];
            #pragma unroll
            for (int mt = 0; mt < 2; mt++)
                ldsm4(a[mt], &As[buf][wm * 32 + mt * 16 + la][ks * 16 + ha * 8]);
            #pragma unroll
            for (int nb = 0; nb < 4; nb++) {
                uint32_t b[4];
                ldsm4t(b, &Bs[buf][ks * 16 + (mi & 1) * 8 + r8][wn * 64 + nb * 16 + (mi >> 1) * 8]);
                #pragma unroll
                for (int mt = 0; mt < 2; mt++) {
                    mma16816(acc[mt][2 * nb],     a[mt], b[0], b[1]);
                    mma16816(acc[mt][2 * nb + 1], a[mt], b[2], b[3]);
                }
            }
        }
        __syncthreads();
    }

    const int part = o0 >> 8;
    __half* dst = (part == 0) ? g_q16 : ((part == 1) ? g_k16 : g_v16);
    const float scale = (part == 0) ? (0.125f * LOG2E) : 1.0f;
    #pragma unroll
    for (int mt = 0; mt < 2; mt++) {
        int o_lo = o0 + wm * 32 + mt * 16 + g;
        float b_lo = qkv_b[o_lo], b_hi = qkv_b[o_lo + 8];
        int c_lo = o_lo & 255;
        #pragma unroll
        for (int nt = 0; nt < 8; nt++) {
            int j = j0 + wn * 64 + nt * 8 + 2 * t4;
            *(uint32_t*)&dst[((size_t)n * CC + c_lo) * HWD + j] =
                pack2((acc[mt][nt][0] + b_lo) * scale, (acc[mt][nt][1] + b_lo) * scale);
            *(uint32_t*)&dst[((size_t)n * CC + c_lo + 8) * HWD + j] =
                pack2((acc[mt][nt][2] + b_hi) * scale, (acc[mt][nt][3] + b_hi) * scale);
        }
    }
}

// ---------------- fp16 tensor-core GEMM: proj + residual + mask ----------------
__global__ __launch_bounds__(256, 2) void gemm_proj16_kernel(
    const float* __restrict__ x, const float* __restrict__ mask,
    const float* __restrict__ pb, float* __restrict__ out)
{
    const int n  = blockIdx.z;
    const int o0 = blockIdx.y * 128;
    const int j0 = blockIdx.x * 128;
    __shared__ __align__(16) __half As[2][128][40];
    __shared__ __align__(16) __half Bs[2][32][136];

    const int tid = threadIdx.x, w = tid >> 5, lane = tid & 31;
    const int wm = w >> 1, wn = w & 1;
    const int g = lane >> 2, t4 = lane & 3, mi = lane >> 3, r8 = lane & 7;
    const int la = lane & 15, ha = lane >> 4;
    const __half* Bsrc = g_ao16 + (size_t)n * CC * HWD;

    auto prefetch = [&](int buf, int k0) {
        #pragma unroll
        for (int i = 0; i < 2; i++) {
            int s = tid + 256 * i;
            int row = s >> 2, c8 = (s & 3) * 8;
            cp16(&As[buf][row][c8], &g_pw16[(size_t)(o0 + row) * CC + k0 + c8]);
        }
        #pragma unroll
        for (int i = 0; i < 2; i++) {
            int s = tid + 256 * i;
            int row = s >> 4, c8 = (s & 15) * 8;
            cp16(&Bs[buf][row][c8], &Bsrc[(size_t)(k0 + row) * HWD + j0 + c8]);
        }
        asm volatile("cp.async.commit_group;\n");
    };

    float acc[2][8][4] = {};
    prefetch(0, 0);
    for (int c = 0; c < 8; c++) {
        int buf = c & 1;
        if (c + 1 < 8) { prefetch(buf ^ 1, (c + 1) * 32); asm volatile("cp.async.wait_group 1;\n"); }
        else           { asm volatile("cp.async.wait_group 0;\n"); }
        __syncthreads();
        #pragma unroll
        for (int ks = 0; ks < 2; ks++) {
            uint32_t a[2][4];
            #pragma unroll
            for (int mt = 0; mt < 2; mt++)
                ldsm4(a[mt], &As[buf][wm * 32 + mt * 16 + la][ks * 16 + ha * 8]);
            #pragma unroll
            for (int nb = 0; nb < 4; nb++) {
                uint32_t b[4];
                ldsm4t(b, &Bs[buf][ks * 16 + (mi & 1) * 8 + r8][wn * 64 + nb * 16 + (mi >> 1) * 8]);
                #pragma unroll
                for (int mt = 0; mt < 2; mt++) {
                    mma16816(acc[mt][2 * nb],     a[mt], b[0], b[1]);
                    mma16816(acc[mt][2 * nb + 1], a[mt], b[2], b[3]);
                }
            }
        }
        __syncthreads();
    }

    #pragma unroll
    for (int mt = 0; mt < 2; mt++) {
        int o_lo = o0 + wm * 32 + mt * 16 + g;
        float b_lo = pb[o_lo], b_hi = pb[o_lo + 8];
        #pragma unroll
        for (int nt = 0; nt < 8; nt++) {
            int j = j0 + wn * 64 + nt * 8 + 2 * t4;
            float2 mv = *(const float2*)&mask[(size_t)n * HWD + j];
            size_t off = ((size_t)n * CC + o_lo) * HWD + j;
            float2 xv = *(const float2*)&x[off];
            float2 r;
            r.x = (xv.x + acc[mt][nt][0] + b_lo) * mv.x;
            r.y = (xv.y + acc[mt][nt][1] + b_lo) * mv.y;
            *(float2*)&out[off] = r;
            size_t off2 = off + 8 * HWD;
            float2 xv2 = *(const float2*)&x[off2];
            float2 r2;
            r2.x = (xv2.x + acc[mt][nt][2] + b_hi) * mv.x;
            r2.y = (xv2.y + acc[mt][nt][3] + b_hi) * mv.y;
            *(float2*)&out[off2] = r2;
        }
    }
}

// ---------------- Flash attention: 8 warps x 16q, 3-stage pipeline ----------------
#define KP 72
#define QP 136
#define KVST 4608                 // halves per K (or V) stage
#define SMQ  8704                 // halves for Q region
#define SM_ATTN_BYTES ((SMQ + 6 * KVST) * 2)   // 72704 B

__global__ __launch_bounds__(256, 2) void attn_kernel() {
    extern __shared__ __align__(16) __half SMh[];
    const int n = blockIdx.y >> 2, h = blockIdx.y & 3;
    const int q0 = blockIdx.x * 128;
    const size_t base = (size_t)(n * CC + h * HD) * HWD;
    const __half* qg = g_q16 + base;
    const __half* kg = g_k16 + base;
    const __half* vg = g_v16 + base;

    const int tid = threadIdx.x, w = tid >> 5, lane = tid & 31;
    const int g = lane >> 2, t4 = lane & 3, mi = lane >> 3, r8 = lane & 7;

    // stage Q [64 hd][128 q]
    #pragma unroll
    for (int i = 0; i < 4; i++) {
        int s = tid + 256 * i;
        int row = s >> 4, c8 = (s & 15) * 8;
        *(uint4*)&SMh[row * QP + c8] = *(const uint4*)&qg[(size_t)row * HWD + q0 + c8];
    }

    auto prefetch = [&](int stg, int c) {
        int jc = c * 64;
        __half* Kb = &SMh[SMQ + stg * KVST];
        __half* Vb = &SMh[SMQ + 3 * KVST + stg * KVST];
        #pragma unroll
        for (int i = 0; i < 2; i++) {
            int s = tid + 256 * i;
            int row = s >> 3, c8 = (s & 7) * 8;
            cp16(&Kb[row * KP + c8], &kg[(size_t)row * HWD + jc + c8]);
            cp16(&Vb[row * KP + c8], &vg[(size_t)row * HWD + jc + c8]);
        }
        asm volatile("cp.async.commit_group;\n");
    };
    prefetch(0, 0);
    prefetch(1, 1);
    __syncthreads();

    // Q fragments (16 q-rows per warp)
    uint32_t aq[4][4];
    #pragma unroll
    for (int kt = 0; kt < 4; kt++)
        ldsm4t(aq[kt], &SMh[(kt * 16 + (mi >> 1) * 8 + r8) * QP + w * 16 + (mi & 1) * 8]);

    float o[8][4] = {};
    float mrun0 = -INFINITY, mrun1 = -INFINITY;
    float l0 = 0.f, l1 = 0.f;

    for (int c = 0; c < 64; c++) {
        if (c < 63) asm volatile("cp.async.wait_group 1;\n");
        else        asm volatile("cp.async.wait_group 0;\n");
        __syncthreads();
        if (c + 2 < 64) prefetch((c + 2) % 3, c + 2);

        const __half* Kb = &SMh[SMQ + (c % 3) * KVST];
        const __half* Vb = &SMh[SMQ + 3 * KVST + (c % 3) * KVST];

        // S = Q K^T  (16 x 64 per warp)
        float s[8][4] = {};
        #pragma unroll
        for (int kt = 0; kt < 4; kt++) {
            #pragma unroll
            for (int ntp = 0; ntp < 4; ntp++) {
                uint32_t b[4];
                ldsm4t(b, &Kb[(kt * 16 + (mi & 1) * 8 + r8) * KP + ntp * 16 + (mi >> 1) * 8]);
                mma16816(s[2 * ntp],     aq[kt], b[0], b[1]);
                mma16816(s[2 * ntp + 1], aq[kt], b[2], b[3]);
            }
        }

        // online softmax
        float mx0 = -INFINITY, mx1 = -INFINITY;
        #pragma unroll
        for (int nt = 0; nt < 8; nt++) {
            mx0 = fmaxf(mx0, fmaxf(s[nt][0], s[nt][1]));
            mx1 = fmaxf(mx1, fmaxf(s[nt][2], s[nt][3]));
        }
        mx0 = fmaxf(mx0, __shfl_xor_sync(0xffffffffu, mx0, 1));
        mx0 = fmaxf(mx0, __shfl_xor_sync(0xffffffffu, mx0, 2));
        mx1 = fmaxf(mx1, __shfl_xor_sync(0xffffffffu, mx1, 1));
        mx1 = fmaxf(mx1, __shfl_xor_sync(0xffffffffu, mx1, 2));
        float mnew0 = fmaxf(mrun0, mx0), mnew1 = fmaxf(mrun1, mx1);
        float corr0 = ex2(mrun0 - mnew0), corr1 = ex2(mrun1 - mnew1);
        mrun0 = mnew0; mrun1 = mnew1;

        uint32_t ph[8], phh[8];
        __half2 hs0 = __floats2half2_rn(0.f, 0.f), hs1 = hs0;
        #pragma unroll
        for (int nt = 0; nt < 8; nt++) {
            ph[nt]  = h2ex2(pack2(s[nt][0] - mnew0, s[nt][1] - mnew0));
            phh[nt] = h2ex2(pack2(s[nt][2] - mnew1, s[nt][3] - mnew1));
            hs0 = __hadd2(hs0, *(__half2*)&ph[nt]);
            hs1 = __hadd2(hs1, *(__half2*)&phh[nt]);
        }
        l0 = l0 * corr0 + __low2float(hs0) + __high2float(hs0);
        l1 = l1 * corr1 + __low2float(hs1) + __high2float(hs1);
        #pragma unroll
        for (int nt = 0; nt < 8; nt++) {
            o[nt][0] *= corr0; o[nt][1] *= corr0;
            o[nt][2] *= corr1; o[nt][3] *= corr1;
        }

        // O += P V
        #pragma unroll
        for (int kt = 0; kt < 4; kt++) {
            uint32_t ap[4] = { ph[2 * kt], phh[2 * kt], ph[2 * kt + 1], phh[2 * kt + 1] };
            #pragma unroll
            for (int ntp = 0; ntp < 4; ntp++) {
                uint32_t b[4];
                ldsm4(b, &Vb[(ntp * 16 + (mi >> 1) * 8 + r8) * KP + kt * 16 + (mi & 1) * 8]);
                mma16816(o[2 * ntp],     ap, b[0], b[1]);
                mma16816(o[2 * ntp + 1], ap, b[2], b[3]);
            }
        }
    }

    // finalize: quad row-sums, normalize, stage [q][d], transposed store
    l0 += __shfl_xor_sync(0xffffffffu, l0, 1);
    l0 += __shfl_xor_sync(0xffffffffu, l0, 2);
    l1 += __shfl_xor_sync(0xffffffffu, l1, 1);
    l1 += __shfl_xor_sync(0xffffffffu, l1, 2);
    float li0 = 1.0f / l0, li1 = 1.0f / l1;

    __syncthreads();
    __half* Ostage = &SMh[SMQ];       // 128 x KP halves fits in 3 stages of K region
    int qr = w * 16 + g;
    #pragma unroll
    for (int nt = 0; nt < 8; nt++) {
        int d0 = nt * 8 + 2 * t4;
        *(uint32_t*)&Ostage[qr * KP + d0]       = pack2(o[nt][0] * li0, o[nt][1] * li0);
        *(uint32_t*)&Ostage[(qr + 8) * KP + d0] = pack2(o[nt][2] * li1, o[nt][3] * li1);
    }
    __syncthreads();
    __half* aob = g_ao16 + base;
    #pragma unroll
    for (int i = 0; i < 16; i++) {
        int f = tid + 256 * i;
        int qp = f & 63, d = f >> 6;
        __half2 hv = __halves2half2(Ostage[(2 * qp) * KP + d], Ostage[(2 * qp + 1) * KP + d]);
        *(uint32_t*)&aob[(size_t)d * HWD + q0 + 2 * qp] = *(uint32_t*)&hv;
    }
}

__global__ void copy_mask_kernel(const float* __restrict__ mask, float* __restrict__ out) {
    int i = blockIdx.x * blockDim.x + threadIdx.x;
    if (i < NB * HWD) out[i] = mask[i];
}

// ---------------------------------------------------------------------------
extern "C" void kernel_launch(void* const* d_in, const int* in_sizes, int n_in,
                              void* d_out, int out_size) {
    const float* x      = (const float*)d_in[0];
    const float* mask   = (const float*)d_in[1];
    const float* norm_w = (const float*)d_in[2];
    const float* norm_b = (const float*)d_in[3];
    const float* qkv_w  = (const float*)d_in[4];
    const float* qkv_b  = (const float*)d_in[5];
    const float* proj_w = (const float*)d_in[6];
    const float* proj_b = (const float*)d_in[7];
    float* out = (float*)d_out;

    cudaFuncSetAttribute(attn_kernel, cudaFuncAttributeMaxDynamicSharedMemorySize, SM_ATTN_BYTES);

    gn_part_kernel<<<256, 256>>>(x);
    conv_w_kernel<<<768, 256>>>(qkv_w, proj_w);
    prep_xn_kernel<<<NB * CC, 256>>>(x, norm_w, norm_b);
    gemm_qkv16_kernel<<<dim3(HWD / 128, (3 * CC) / 128, NB), 256>>>(qkv_b);
    attn_kernel<<<dim3(HWD / 128, NB * NH), 256, SM_ATTN_BYTES>>>();
    gemm_proj16_kernel<<<dim3(HWD / 128, CC / 128, NB), 256>>>(x, mask, proj_b, out);
    if (out_size >= NB * CC * HWD + NB * HWD)
        copy_mask_kernel<<<(NB * HWD) / 256, 256>>>(mask, out + (size_t)NB * CC * HWD);
}